// round 1
// baseline (speedup 1.0000x reference)
#include <cuda_runtime.h>
#include <math.h>

// ---------------------------------------------------------------------------
// Problem constants
// ---------------------------------------------------------------------------
constexpr int IH = 100, IW = 100, HWN = IH * IW;   // 10000
constexpr int BATCH = 2;
constexpr int NA = 9;          // anchors
constexpr int C = 256;         // tower channels
constexpr int KTOT = NA * C;   // 2304 (1x1 reduction dim)

// ---------------------------------------------------------------------------
// Scratch (device globals -- no allocations allowed)
// ---------------------------------------------------------------------------
__device__ float g_t0[BATCH * C * HWN];
__device__ float g_t1[BATCH * C * HWN];
__device__ float g_t2[BATCH * C * HWN];
__device__ float g_t3[BATCH * C * HWN];
__device__ float g_boxreg[BATCH * 36 * HWN];
__device__ float g_dcls[NA * BATCH * C * HWN];   // [i_vmap][j_batch][co][hw]
__device__ float g_dreg[NA * BATCH * C * HWN];
__device__ float g_refine[BATCH * 36 * HWN];

// ---------------------------------------------------------------------------
// 3x3 conv, pad=1, optional ReLU.  in [B,Cin,H,W] -> out [B,Cout,H,W]
// Tile: 16x8 spatial, 32 output channels, 256 threads, 4co x 4pix regs/thread
// ---------------------------------------------------------------------------
constexpr int CV_TW = 16, CV_TH = 8, CV_COT = 32, CV_CIT = 16;
constexpr int CV_PITCH = 20;

__global__ void __launch_bounds__(256) conv3x3_kernel(
    const float* __restrict__ in, const float* __restrict__ wgt,
    const float* __restrict__ bias, float* __restrict__ out,
    int Cin, int Cout, int relu)
{
    __shared__ float s_in[CV_CIT][CV_TH + 2][CV_PITCH];
    __shared__ __align__(16) float s_w[CV_CIT][9][CV_COT];

    const int nco = (Cout + CV_COT - 1) / CV_COT;
    const int z = blockIdx.z;
    const int b = z / nco;
    const int co_base = (z % nco) * CV_COT;
    const int tx0 = blockIdx.x * CV_TW;
    const int ty0 = blockIdx.y * CV_TH;

    const int tid = threadIdx.x;
    const int cg = tid >> 5;          // 0..7  (co group of 4)
    const int pg = tid & 31;          // 0..31 (pixel group of 4)
    const int prow = pg >> 2;         // 0..7
    const int pxb = (pg & 3) * 4;     // 0,4,8,12

    float acc[4][4];
#pragma unroll
    for (int q = 0; q < 4; q++)
#pragma unroll
        for (int p = 0; p < 4; p++) acc[q][p] = 0.f;

    for (int ci0 = 0; ci0 < Cin; ci0 += CV_CIT) {
        // load input tile with halo (zero-padded)
        for (int e = tid; e < CV_CIT * (CV_TH + 2) * (CV_TW + 2); e += 256) {
            int ci = e / ((CV_TH + 2) * (CV_TW + 2));
            int r = e % ((CV_TH + 2) * (CV_TW + 2));
            int iy = r / (CV_TW + 2);
            int ix = r % (CV_TW + 2);
            int gy = ty0 + iy - 1, gx = tx0 + ix - 1;
            float v = 0.f;
            if (gy >= 0 && gy < IH && gx >= 0 && gx < IW)
                v = in[(((size_t)b * Cin + ci0 + ci) * IH + gy) * IW + gx];
            s_in[ci][iy][ix] = v;
        }
        // load weights
        for (int e = tid; e < CV_CIT * 9 * CV_COT; e += 256) {
            int ci = e / (9 * CV_COT);
            int k = (e / CV_COT) % 9;
            int co = e % CV_COT;
            float v = 0.f;
            int gco = co_base + co;
            if (gco < Cout)
                v = wgt[(((size_t)gco * Cin) + ci0 + ci) * 9 + k];
            s_w[ci][k][co] = v;
        }
        __syncthreads();

#pragma unroll 4
        for (int ci = 0; ci < CV_CIT; ci++) {
#pragma unroll
            for (int ky = 0; ky < 3; ky++) {
                float r6[6];
#pragma unroll
                for (int jx = 0; jx < 6; jx++)
                    r6[jx] = s_in[ci][prow + ky][pxb + jx];
#pragma unroll
                for (int kx = 0; kx < 3; kx++) {
                    float4 w4 = *(const float4*)&s_w[ci][ky * 3 + kx][cg * 4];
                    float wv[4] = {w4.x, w4.y, w4.z, w4.w};
#pragma unroll
                    for (int q = 0; q < 4; q++)
#pragma unroll
                        for (int p = 0; p < 4; p++)
                            acc[q][p] = fmaf(wv[q], r6[p + kx], acc[q][p]);
                }
            }
        }
        __syncthreads();
    }

#pragma unroll
    for (int q = 0; q < 4; q++) {
        int co = co_base + cg * 4 + q;
        if (co >= Cout) continue;
        float bv = bias ? bias[co] : 0.f;
#pragma unroll
        for (int p = 0; p < 4; p++) {
            int gy = ty0 + prow, gx = tx0 + pxb + p;
            if (gy < IH && gx < IW) {
                float v = acc[q][p] + bv;
                if (relu) v = fmaxf(v, 0.f);
                out[(((size_t)b * Cout + co) * IH + gy) * IW + gx] = v;
            }
        }
    }
}

// ---------------------------------------------------------------------------
// Deformable conv v1, 3x3, pad 1, no bias.
// Block: vmap-slot i, feature batch j, 64 co, 8x8 pixel tile.
// Offsets derived in-kernel from box_reg (semantics collapse to:
//    py = y + gx[kx], px = x + gy[ky], with the A/B reshape twist n = 2i+j).
// ---------------------------------------------------------------------------
constexpr int D_CIT = 8;
constexpr int D_SMEM = 4 * 576 * 2       /* s_off shorts */
                     + 4 * 576 * 4       /* s_wt  */
                     + D_CIT * 576 * 4   /* s_v   */
                     + D_CIT * 9 * 64 * 4 /* s_w  */;   // = 50688 B

__global__ void __launch_bounds__(256) deform_kernel(
    const float* __restrict__ feat, const float* __restrict__ boxreg,
    const float* __restrict__ wgt, float* __restrict__ out)
{
    extern __shared__ unsigned char smraw[];
    short* s_off = (short*)smraw;                       // [4][576]
    float* s_wt  = (float*)(smraw + 4608);              // [4][576]
    float* s_v   = (float*)(smraw + 13824);             // [CIT][576]
    float* s_w   = (float*)(smraw + 32256);             // [CIT][9][64]

    const int z = blockIdx.z;
    const int iv = z >> 3;            // vmap slot 0..8
    const int jb = (z >> 2) & 1;      // feature batch
    const int cot = z & 3;
    const int co_base = cot * 64;
    const int x0 = blockIdx.x * 8, y0 = blockIdx.y * 8;
    const int tid = threadIdx.x;

    const int n = iv * 2 + jb;        // flat index in (B*A) order (b*A + a)
    const int bn = n / 9, an = n % 9; // box_reg batch/anchor (may differ from jb!)

    // ------- phase 0: per-pixel bilinear sample precompute (64 pixels x 9 k)
    if (tid < 64) {
        int row = tid >> 3, col = tid & 7;
        int y = y0 + row, x = x0 + col;
        bool pv = (y < IH) && (x < IW);
        float c0 = 0.f, c1 = 0.f, c2 = 0.f, c3 = 0.f;
        if (pv) {
            const float* rp = boxreg + ((size_t)bn * 36 + an * 4) * HWN + y * IW + x;
            c0 = rp[0]; c1 = rp[HWN]; c2 = rp[2 * HWN]; c3 = rp[3 * HWN];
        }
        float size = 2.f * exp2f((float)(an / 3) * (1.f / 3.f));
        int ari = an % 3;
        float ar = (ari == 0) ? 0.5f : (ari == 1 ? 1.f : 2.f);
        float wa = sqrtf(size * size / ar);
        float ha = ar * wa;
        float e2 = expf(c2), e3 = expf(c3);
        float tlx = wa * c0 - 0.5f * wa * e2, whx = wa * e2;
        float tly = ha * c1 - 0.5f * ha * e3, why = ha * e3;
#pragma unroll
        for (int k = 0; k < 9; k++) {
            int ki = k / 3, kj = k % 3;
            float gx = tlx + whx * (0.5f * kj);
            float gy = tly + why * (0.5f * ki);
            float py = (float)y + gx;     // flip(2): x-grid drives y samples
            float px = (float)x + gy;
            float fy = floorf(py), fx = floorf(px);
            float ly = py - fy, lx = px - fx;
            int iy0 = (int)fy, ix0 = (int)fx;
#pragma unroll
            for (int c = 0; c < 4; c++) {
                int dy = c >> 1, dx = c & 1;
                int yy = iy0 + dy, xx = ix0 + dx;
                bool vc = pv && (yy >= 0) && (yy < IH) && (xx >= 0) && (xx < IW);
                float wv = (dy ? ly : 1.f - ly) * (dx ? lx : 1.f - lx);
                wv = vc ? wv : 0.f;
                int yc = min(max(yy, 0), IH - 1);
                int xc = min(max(xx, 0), IW - 1);
                s_off[c * 576 + k * 64 + tid] = (short)(yc * IW + xc);
                s_wt[c * 576 + k * 64 + tid] = wv;
            }
        }
    }
    __syncthreads();

    float acc[4][4];
#pragma unroll
    for (int q = 0; q < 4; q++)
#pragma unroll
        for (int p = 0; p < 4; p++) acc[q][p] = 0.f;

    const int cg = tid >> 4;   // co group of 4
    const int pg = tid & 15;   // pixel group of 4
    const float* fb = feat + (size_t)jb * C * HWN;

    for (int ci0 = 0; ci0 < C; ci0 += D_CIT) {
        // weights [ci][k][co]
        for (int e = tid; e < D_CIT * 9 * 64; e += 256) {
            int ci = e / 576;
            int rem = e % 576;
            int k = rem >> 6, co = rem & 63;
            s_w[e] = wgt[((size_t)(co_base + co) * C + ci0 + ci) * 9 + k];
        }
        // gather V[ci][k*64+pix] via 4-corner bilinear
        for (int e = tid; e < D_CIT * 576; e += 256) {
            int ci = e / 576;
            int s = e % 576;
            const float* pl = fb + (size_t)(ci0 + ci) * HWN;
            float v = s_wt[s]          * pl[s_off[s]]
                    + s_wt[576 + s]    * pl[s_off[576 + s]]
                    + s_wt[1152 + s]   * pl[s_off[1152 + s]]
                    + s_wt[1728 + s]   * pl[s_off[1728 + s]];
            s_v[e] = v;
        }
        __syncthreads();

#pragma unroll 2
        for (int ci = 0; ci < D_CIT; ci++) {
#pragma unroll
            for (int k = 0; k < 9; k++) {
                float4 w4 = *(const float4*)&s_w[(ci * 9 + k) * 64 + cg * 4];
                float4 v4 = *(const float4*)&s_v[ci * 576 + k * 64 + pg * 4];
                float wv[4] = {w4.x, w4.y, w4.z, w4.w};
                float vv[4] = {v4.x, v4.y, v4.z, v4.w};
#pragma unroll
                for (int q = 0; q < 4; q++)
#pragma unroll
                    for (int p = 0; p < 4; p++)
                        acc[q][p] = fmaf(wv[q], vv[p], acc[q][p]);
            }
        }
        __syncthreads();
    }

#pragma unroll
    for (int q = 0; q < 4; q++) {
        int co = co_base + cg * 4 + q;
        float* op = out + ((size_t)(iv * 2 + jb) * C + co) * HWN;
#pragma unroll
        for (int p = 0; p < 4; p++) {
            int pix = pg * 4 + p;
            int row = pix >> 3, col = pix & 7;
            int y = y0 + row, x = x0 + col;
            if (y < IH && x < IW) op[y * IW + x] = acc[q][p];
        }
    }
}

// ---------------------------------------------------------------------------
// 1x1 conv over cat features with fused input ReLU.
// in layout: [(a*B + b)*C + c] * HWN  (deform output order == cat order)
// ---------------------------------------------------------------------------
__global__ void __launch_bounds__(256) conv1x1_kernel(
    const float* __restrict__ in, const float* __restrict__ wgt,
    const float* __restrict__ bias, float* __restrict__ out, int Cout)
{
    __shared__ __align__(16) float s_in[16][64];
    __shared__ __align__(16) float s_w[16][64];

    const int b = blockIdx.z;
    const int co_base = blockIdx.y * 64;
    const int p0 = blockIdx.x * 64;
    const int tid = threadIdx.x;

    float acc[4][4];
#pragma unroll
    for (int q = 0; q < 4; q++)
#pragma unroll
        for (int p = 0; p < 4; p++) acc[q][p] = 0.f;

    for (int k0 = 0; k0 < KTOT; k0 += 16) {
        for (int e = tid; e < 16 * 64; e += 256) {
            int kk = e >> 6, p = e & 63;
            int k = k0 + kk;
            int aidx = k >> 8, c = k & 255;
            int pix = p0 + p;
            float v = 0.f;
            if (pix < HWN)
                v = in[((size_t)(aidx * 2 + b) * C + c) * HWN + pix];
            s_in[kk][p] = fmaxf(v, 0.f);
            float wv = 0.f;
            if (co_base + p < Cout)
                wv = wgt[(size_t)(co_base + p) * KTOT + k];
            s_w[kk][p] = wv;
        }
        __syncthreads();

        const int cg = tid >> 4, pg = tid & 15;
#pragma unroll
        for (int kk = 0; kk < 16; kk++) {
            float4 w4 = *(const float4*)&s_w[kk][cg * 4];
            float4 v4 = *(const float4*)&s_in[kk][pg * 4];
            float wv[4] = {w4.x, w4.y, w4.z, w4.w};
            float vv[4] = {v4.x, v4.y, v4.z, v4.w};
#pragma unroll
            for (int q = 0; q < 4; q++)
#pragma unroll
                for (int p = 0; p < 4; p++)
                    acc[q][p] = fmaf(wv[q], vv[p], acc[q][p]);
        }
        __syncthreads();
    }

    const int cg = tid >> 4, pg = tid & 15;
#pragma unroll
    for (int q = 0; q < 4; q++) {
        int co = co_base + cg * 4 + q;
        if (co >= Cout) continue;
        float bv = bias[co];
#pragma unroll
        for (int p = 0; p < 4; p++) {
            int pix = p0 + pg * 4 + p;
            if (pix < HWN)
                out[((size_t)b * Cout + co) * HWN + pix] = acc[q][p] + bv;
        }
    }
}

// ---------------------------------------------------------------------------
// delta head: o1 = box_reg, o2 = refine
// ---------------------------------------------------------------------------
__global__ void delta_kernel(const float* __restrict__ boxreg,
                             const float* __restrict__ refine,
                             float* __restrict__ out)
{
    int t = blockIdx.x * blockDim.x + threadIdx.x;
    if (t >= BATCH * NA * HWN) return;
    int pix = t % HWN;
    int r = t / HWN;
    int a = r % NA;
    int b = r / NA;
    size_t base = ((size_t)b * 36 + a * 4) * HWN + pix;
    float o10 = boxreg[base], o11 = boxreg[base + HWN];
    float o12 = boxreg[base + 2 * HWN], o13 = boxreg[base + 3 * HWN];
    float o20 = refine[base], o21 = refine[base + HWN];
    float o22 = refine[base + 2 * HWN], o23 = refine[base + 3 * HWN];
    out[base]           = o10 + expf(o12) * o20;
    out[base + HWN]     = o11 + expf(o13) * o21;
    out[base + 2 * HWN] = o12 + o22;
    out[base + 3 * HWN] = o13 + o23;
}

// ---------------------------------------------------------------------------
// launch
// ---------------------------------------------------------------------------
extern "C" void kernel_launch(void* const* d_in, const int* in_sizes, int n_in,
                              void* d_out, int out_size)
{
    const float* x       = (const float*)d_in[0];
    const float* cls_w   = (const float*)d_in[1];
    const float* cls_b   = (const float*)d_in[2];
    const float* reg_w   = (const float*)d_in[3];
    const float* reg_b   = (const float*)d_in[4];
    const float* pred_w  = (const float*)d_in[5];
    const float* pred_b  = (const float*)d_in[6];
    const float* dcls_w  = (const float*)d_in[7];
    const float* dreg_w  = (const float*)d_in[8];
    const float* logit_w = (const float*)d_in[9];
    const float* logit_b = (const float*)d_in[10];
    const float* refine_w = (const float*)d_in[11];
    const float* refine_b = (const float*)d_in[12];
    float* out = (float*)d_out;

    float *t0, *t1, *t2, *t3, *boxreg, *dcls, *dreg, *refine;
    cudaGetSymbolAddress((void**)&t0, g_t0);
    cudaGetSymbolAddress((void**)&t1, g_t1);
    cudaGetSymbolAddress((void**)&t2, g_t2);
    cudaGetSymbolAddress((void**)&t3, g_t3);
    cudaGetSymbolAddress((void**)&boxreg, g_boxreg);
    cudaGetSymbolAddress((void**)&dcls, g_dcls);
    cudaGetSymbolAddress((void**)&dreg, g_dreg);
    cudaGetSymbolAddress((void**)&refine, g_refine);

    const size_t WSTEP = (size_t)C * C * 9;
    dim3 cgrid((IW + CV_TW - 1) / CV_TW, (IH + CV_TH - 1) / CV_TH, 8 * BATCH);

    // cls tower: x -> t0 -> t1 -> t0 -> t1   (cf = t1)
    conv3x3_kernel<<<cgrid, 256>>>(x,  cls_w + 0 * WSTEP, cls_b + 0 * C, t0, C, C, 1);
    conv3x3_kernel<<<cgrid, 256>>>(t0, cls_w + 1 * WSTEP, cls_b + 1 * C, t1, C, C, 1);
    conv3x3_kernel<<<cgrid, 256>>>(t1, cls_w + 2 * WSTEP, cls_b + 2 * C, t0, C, C, 1);
    conv3x3_kernel<<<cgrid, 256>>>(t0, cls_w + 3 * WSTEP, cls_b + 3 * C, t1, C, C, 1);
    // reg tower: x -> t2 -> t3 -> t2 -> t3   (rf = t3)
    conv3x3_kernel<<<cgrid, 256>>>(x,  reg_w + 0 * WSTEP, reg_b + 0 * C, t2, C, C, 1);
    conv3x3_kernel<<<cgrid, 256>>>(t2, reg_w + 1 * WSTEP, reg_b + 1 * C, t3, C, C, 1);
    conv3x3_kernel<<<cgrid, 256>>>(t3, reg_w + 2 * WSTEP, reg_b + 2 * C, t2, C, C, 1);
    conv3x3_kernel<<<cgrid, 256>>>(t2, reg_w + 3 * WSTEP, reg_b + 3 * C, t3, C, C, 1);

    // pred conv: rf -> box_reg  [B,36,H,W], no relu
    dim3 pgrid((IW + CV_TW - 1) / CV_TW, (IH + CV_TH - 1) / CV_TH, 2 * BATCH);
    conv3x3_kernel<<<pgrid, 256>>>(t3, pred_w, pred_b, boxreg, C, 36, 0);

    // deformable convs
    cudaFuncSetAttribute(deform_kernel,
                         cudaFuncAttributeMaxDynamicSharedMemorySize, D_SMEM);
    dim3 dgrid((IW + 7) / 8, (IH + 7) / 8, NA * BATCH * 4);
    deform_kernel<<<dgrid, 256, D_SMEM>>>(t1, boxreg, dcls_w, dcls);
    deform_kernel<<<dgrid, 256, D_SMEM>>>(t3, boxreg, dreg_w, dreg);

    // 1x1 heads (relu applied to inputs inside)
    dim3 lgrid((HWN + 63) / 64, (720 + 63) / 64, BATCH);
    conv1x1_kernel<<<lgrid, 256>>>(dcls, logit_w, logit_b, out, 720);
    dim3 rgrid((HWN + 63) / 64, 1, BATCH);
    conv1x1_kernel<<<rgrid, 256>>>(dreg, refine_w, refine_b, refine, 36);

    // delta written after logits in d_out
    delta_kernel<<<(BATCH * NA * HWN + 255) / 256, 256>>>(
        boxreg, refine, out + (size_t)BATCH * 720 * HWN);
}

// round 5
// speedup vs baseline: 1.3906x; 1.3906x over previous
#include <cuda_runtime.h>
#include <math.h>

// ---------------------------------------------------------------------------
// Problem constants
// ---------------------------------------------------------------------------
constexpr int IH = 100, IW = 100, HWN = IH * IW;
constexpr int BATCH = 2;
constexpr int NA = 9;
constexpr int C = 256;
constexpr int KTOT = NA * C;   // 2304

// ---------------------------------------------------------------------------
// Scratch
// ---------------------------------------------------------------------------
__device__ float g_t0[BATCH * C * HWN];
__device__ float g_t1[BATCH * C * HWN];
__device__ float g_t2[BATCH * C * HWN];
__device__ float g_t3[BATCH * C * HWN];
__device__ float g_boxreg[BATCH * 36 * HWN];
__device__ float g_dcls[NA * BATCH * C * HWN];
__device__ float g_dreg[NA * BATCH * C * HWN];
__device__ float g_refine[BATCH * 36 * HWN];

// ---------------------------------------------------------------------------
// Packed fp32x2 helpers
// ---------------------------------------------------------------------------
__device__ __forceinline__ unsigned long long splat2(float x) {
    unsigned long long r;
    asm("mov.b64 %0, {%1, %1};" : "=l"(r) : "f"(x));
    return r;
}
__device__ __forceinline__ void ffma2(unsigned long long& acc,
                                      unsigned long long a,
                                      unsigned long long b) {
    asm("fma.rn.f32x2 %0, %1, %2, %0;" : "+l"(acc) : "l"(a), "l"(b));
}
__device__ __forceinline__ float2 unpack2(unsigned long long v) {
    float2 f;
    asm("mov.b64 {%0, %1}, %2;" : "=f"(f.x), "=f"(f.y) : "l"(v));
    return f;
}

// ---------------------------------------------------------------------------
// 3x3 conv, pad=1.  Block: 64 co x (4 rows x 64 cols).  256 thr, 8co x 8px.
// warp = co-group of 8; lane: pr = lane>>3 (row), pc8 = (lane&7)*8 (col base)
// ---------------------------------------------------------------------------
constexpr int CV_CIT = 8;
constexpr int CV_PITCH = 72;

__global__ void __launch_bounds__(256) conv3x3_kernel(
    const float* __restrict__ in, const float* __restrict__ wgt,
    const float* __restrict__ bias, float* __restrict__ out,
    int Cin, int Cout, int relu)
{
    __shared__ __align__(16) float s_in[CV_CIT][6][CV_PITCH];
    __shared__ __align__(16) float s_w[CV_CIT][9][64];

    const int nco = (Cout + 63) / 64;
    const int z = blockIdx.z;
    const int b = z / nco;
    const int co_base = (z % nco) * 64;
    const int tx0 = blockIdx.x * 64;
    const int ty0 = blockIdx.y * 4;

    const int tid = threadIdx.x;
    const int warp = tid >> 5;
    const int lane = tid & 31;
    const int cog8 = warp * 8;
    const int pr = lane >> 3;
    const int pc8 = (lane & 7) * 8;

    unsigned long long acc2[4][8];
#pragma unroll
    for (int q = 0; q < 4; q++)
#pragma unroll
        for (int p = 0; p < 8; p++) acc2[q][p] = 0ull;

    for (int ci0 = 0; ci0 < Cin; ci0 += CV_CIT) {
        // input tile with halo: rows ty0-1 .. ty0+4, cols tx0-1 .. tx0+64
        for (int e = tid; e < CV_CIT * 6 * 66; e += 256) {
            int ci = e / (6 * 66);
            int r = e % (6 * 66);
            int iy = r / 66, ix = r % 66;
            int gy = ty0 + iy - 1, gx = tx0 + ix - 1;
            float v = 0.f;
            if (gy >= 0 && gy < IH && gx >= 0 && gx < IW)
                v = in[(((size_t)b * Cin + ci0 + ci) * IH + gy) * IW + gx];
            s_in[ci][iy][ix] = v;
        }
        // weights [ci][k][co]
        for (int e = tid; e < CV_CIT * 9 * 64; e += 256) {
            int ci = e / 576;
            int k = (e >> 6) % 9;
            int co = e & 63;
            float v = 0.f;
            int gco = co_base + co;
            if (gco < Cout)
                v = wgt[(((size_t)gco * Cin) + ci0 + ci) * 9 + k];
            s_w[ci][k][co] = v;
        }
        __syncthreads();

#pragma unroll 2
        for (int ci = 0; ci < CV_CIT; ci++) {
#pragma unroll
            for (int ky = 0; ky < 3; ky++) {
                const float* rp = &s_in[ci][pr + ky][pc8];
                float4 a0 = *(const float4*)(rp);
                float4 a1 = *(const float4*)(rp + 4);
                float4 a2 = *(const float4*)(rp + 8);
                float r12[12] = {a0.x, a0.y, a0.z, a0.w,
                                 a1.x, a1.y, a1.z, a1.w,
                                 a2.x, a2.y, a2.z, a2.w};
                unsigned long long s12[12];
#pragma unroll
                for (int j = 0; j < 12; j++) s12[j] = splat2(r12[j]);
#pragma unroll
                for (int kx = 0; kx < 3; kx++) {
                    const ulonglong2* wp =
                        (const ulonglong2*)&s_w[ci][ky * 3 + kx][cog8];
                    ulonglong2 wA = wp[0];
                    ulonglong2 wB = wp[1];
                    unsigned long long wq[4] = {wA.x, wA.y, wB.x, wB.y};
#pragma unroll
                    for (int q = 0; q < 4; q++)
#pragma unroll
                        for (int p = 0; p < 8; p++)
                            ffma2(acc2[q][p], wq[q], s12[p + kx]);
                }
            }
        }
        __syncthreads();
    }

    const int gy = ty0 + pr;
#pragma unroll
    for (int q = 0; q < 4; q++) {
        int co0 = co_base + cog8 + 2 * q;
        float b0 = (bias && co0 < Cout) ? bias[co0] : 0.f;
        float b1 = (bias && co0 + 1 < Cout) ? bias[co0 + 1] : 0.f;
#pragma unroll
        for (int p = 0; p < 8; p++) {
            int gx = tx0 + pc8 + p;
            if (gy < IH && gx < IW) {
                float2 v = unpack2(acc2[q][p]);
                if (co0 < Cout) {
                    float r = v.x + b0;
                    if (relu) r = fmaxf(r, 0.f);
                    out[(((size_t)b * Cout + co0) * IH + gy) * IW + gx] = r;
                }
                if (co0 + 1 < Cout) {
                    float r = v.y + b1;
                    if (relu) r = fmaxf(r, 0.f);
                    out[(((size_t)b * Cout + co0 + 1) * IH + gy) * IW + gx] = r;
                }
            }
        }
    }
}

// ---------------------------------------------------------------------------
// Deformable conv v1: block = 128 co x 128 px (8 rows x 16 cols), CIT=4
// thread: cog = tid>>4 (co8 = cog*8), pxg = tid&15 (p8 = pxg*8)
// ---------------------------------------------------------------------------
constexpr int D_CIT = 4;
constexpr int D_NS = 9 * 128;                 // 1152 samples (k,px)
constexpr int D_OFF_B = 4 * D_NS * 2;         // 9216
constexpr int D_WT_B = 4 * D_NS * 4;          // 18432
constexpr int D_V_B = D_CIT * D_NS * 4;       // 18432
constexpr int D_W_B = D_CIT * 9 * 128 * 4;    // 18432
constexpr int D_SMEM = D_OFF_B + D_WT_B + D_V_B + D_W_B;  // 64512

__global__ void __launch_bounds__(256) deform_kernel(
    const float* __restrict__ feat, const float* __restrict__ boxreg,
    const float* __restrict__ wgt, float* __restrict__ out)
{
    extern __shared__ unsigned char smraw[];
    short* s_off = (short*)smraw;                          // [4][1152]
    float* s_wt  = (float*)(smraw + D_OFF_B);              // [4][1152]
    float* s_v   = (float*)(smraw + D_OFF_B + D_WT_B);     // [CIT][1152]
    float* s_w   = (float*)(smraw + D_OFF_B + D_WT_B + D_V_B); // [CIT][9][128]

    const int z = blockIdx.z;
    const int iv = z >> 2;
    const int jb = (z >> 1) & 1;
    const int cot = z & 1;
    const int co_base = cot * 128;
    const int x0 = blockIdx.x * 16, y0 = blockIdx.y * 8;
    const int tid = threadIdx.x;

    const int n = iv * 2 + jb;
    const int bn = n / 9, an = n % 9;

    // ---- phase 0: bilinear sample precompute (128 px x 9 k x 4 corners)
    {
        int px = tid & 127, half = tid >> 7;
        int row = px >> 4, col = px & 15;
        int y = y0 + row, x = x0 + col;
        bool pv = (y < IH) && (x < IW);
        float c0 = 0.f, c1 = 0.f, c2 = 0.f, c3 = 0.f;
        if (pv) {
            const float* rp = boxreg + ((size_t)bn * 36 + an * 4) * HWN + y * IW + x;
            c0 = rp[0]; c1 = rp[HWN]; c2 = rp[2 * HWN]; c3 = rp[3 * HWN];
        }
        float size = 2.f * exp2f((float)(an / 3) * (1.f / 3.f));
        int ari = an % 3;
        float ar = (ari == 0) ? 0.5f : (ari == 1 ? 1.f : 2.f);
        float wa = sqrtf(size * size / ar);
        float ha = ar * wa;
        float e2 = expf(c2), e3 = expf(c3);
        float tlx = wa * c0 - 0.5f * wa * e2, whx = wa * e2;
        float tly = ha * c1 - 0.5f * ha * e3, why = ha * e3;
        int klo = half ? 5 : 0, khi = half ? 9 : 5;
        for (int k = klo; k < khi; k++) {
            int ki = k / 3, kj = k % 3;
            float gx = tlx + whx * (0.5f * kj);
            float gy = tly + why * (0.5f * ki);
            float py = (float)y + gx;   // flip(2): x-grid drives y samples
            float pxx = (float)x + gy;
            float fy = floorf(py), fx = floorf(pxx);
            float ly = py - fy, lx = pxx - fx;
            int iy0 = (int)fy, ix0 = (int)fx;
#pragma unroll
            for (int c = 0; c < 4; c++) {
                int dy = c >> 1, dx = c & 1;
                int yy = iy0 + dy, xx = ix0 + dx;
                bool vc = pv && (yy >= 0) && (yy < IH) && (xx >= 0) && (xx < IW);
                float wv = (dy ? ly : 1.f - ly) * (dx ? lx : 1.f - lx);
                wv = vc ? wv : 0.f;
                int yc = min(max(yy, 0), IH - 1);
                int xc = min(max(xx, 0), IW - 1);
                s_off[c * D_NS + k * 128 + px] = (short)(yc * IW + xc);
                s_wt[c * D_NS + k * 128 + px] = wv;
            }
        }
    }
    __syncthreads();

    unsigned long long acc2[4][8];
#pragma unroll
    for (int q = 0; q < 4; q++)
#pragma unroll
        for (int p = 0; p < 8; p++) acc2[q][p] = 0ull;

    const int cog = tid >> 4;
    const int pxg = tid & 15;
    const int co8 = cog * 8;
    const int p8 = pxg * 8;
    const float* fb = feat + (size_t)jb * C * HWN;

    for (int ci0 = 0; ci0 < C; ci0 += D_CIT) {
        // weights [ci][k][co]
        for (int e = tid; e < D_CIT * 9 * 128; e += 256) {
            int ci = e / D_NS;
            int rem = e % D_NS;
            int k = rem >> 7, co = rem & 127;
            s_w[e] = wgt[((size_t)(co_base + co) * C + ci0 + ci) * 9 + k];
        }
        // gather V[ci][k*128+px]
        for (int e = tid; e < D_CIT * D_NS; e += 256) {
            int ci = e / D_NS;
            int s = e % D_NS;
            const float* pl = fb + (size_t)(ci0 + ci) * HWN;
            float v = s_wt[s]            * pl[s_off[s]]
                    + s_wt[D_NS + s]     * pl[s_off[D_NS + s]]
                    + s_wt[2 * D_NS + s] * pl[s_off[2 * D_NS + s]]
                    + s_wt[3 * D_NS + s] * pl[s_off[3 * D_NS + s]];
            s_v[e] = v;
        }
        __syncthreads();

        for (int ci = 0; ci < D_CIT; ci++) {
#pragma unroll
            for (int k = 0; k < 9; k++) {
                const ulonglong2* wp =
                    (const ulonglong2*)&s_w[(ci * 9 + k) * 128 + co8];
                ulonglong2 wA = wp[0];
                ulonglong2 wB = wp[1];
                unsigned long long wq[4] = {wA.x, wA.y, wB.x, wB.y};
                const float4* vp = (const float4*)&s_v[ci * D_NS + k * 128 + p8];
                float4 v0 = vp[0], v1 = vp[1];
                float vr[8] = {v0.x, v0.y, v0.z, v0.w, v1.x, v1.y, v1.z, v1.w};
                unsigned long long sv[8];
#pragma unroll
                for (int p = 0; p < 8; p++) sv[p] = splat2(vr[p]);
#pragma unroll
                for (int q = 0; q < 4; q++)
#pragma unroll
                    for (int p = 0; p < 8; p++)
                        ffma2(acc2[q][p], wq[q], sv[p]);
            }
        }
        __syncthreads();
    }

    float* ob = out + ((size_t)(iv * 2 + jb) * C) * HWN;
#pragma unroll
    for (int q = 0; q < 4; q++) {
        int co0 = co_base + co8 + 2 * q;
#pragma unroll
        for (int p = 0; p < 8; p++) {
            int px = p8 + p;
            int y = y0 + (px >> 4), x = x0 + (px & 15);
            if (y < IH && x < IW) {
                float2 v = unpack2(acc2[q][p]);
                ob[(size_t)co0 * HWN + y * IW + x] = v.x;
                ob[(size_t)(co0 + 1) * HWN + y * IW + x] = v.y;
            }
        }
    }
}

// ---------------------------------------------------------------------------
// 1x1 conv with fused input ReLU.  Block: 64 co x 256 px, Kchunk=16.
// warp = co-group (co8 = warp*8); lane: p8 = lane*8
// ---------------------------------------------------------------------------
__global__ void __launch_bounds__(256) conv1x1_kernel(
    const float* __restrict__ in, const float* __restrict__ wgt,
    const float* __restrict__ bias, float* __restrict__ out, int Cout)
{
    __shared__ __align__(16) float s_in[16][256];
    __shared__ __align__(16) float s_w[16][64];

    const int b = blockIdx.z;
    const int co_base = blockIdx.y * 64;
    const int p0 = blockIdx.x * 256;
    const int tid = threadIdx.x;
    const int warp = tid >> 5;
    const int lane = tid & 31;
    const int co8 = warp * 8;
    const int p8 = lane * 8;

    unsigned long long acc2[4][8];
#pragma unroll
    for (int q = 0; q < 4; q++)
#pragma unroll
        for (int p = 0; p < 8; p++) acc2[q][p] = 0ull;

    for (int k0 = 0; k0 < KTOT; k0 += 16) {
        for (int e = tid; e < 16 * 256; e += 256) {
            int kk = e >> 8, p = e & 255;
            int k = k0 + kk;
            int aidx = k >> 8, c = k & 255;
            int pix = p0 + p;
            float v = 0.f;
            if (pix < HWN)
                v = in[((size_t)(aidx * 2 + b) * C + c) * HWN + pix];
            s_in[kk][p] = fmaxf(v, 0.f);
        }
        for (int e = tid; e < 16 * 64; e += 256) {
            int kk = e >> 6, co = e & 63;
            float wv = 0.f;
            if (co_base + co < Cout)
                wv = wgt[(size_t)(co_base + co) * KTOT + k0 + kk];
            s_w[kk][co] = wv;
        }
        __syncthreads();

#pragma unroll 4
        for (int kk = 0; kk < 16; kk++) {
            const ulonglong2* wp = (const ulonglong2*)&s_w[kk][co8];
            ulonglong2 wA = wp[0];
            ulonglong2 wB = wp[1];
            unsigned long long wq[4] = {wA.x, wA.y, wB.x, wB.y};
            const float4* vp = (const float4*)&s_in[kk][p8];
            float4 v0 = vp[0], v1 = vp[1];
            float vr[8] = {v0.x, v0.y, v0.z, v0.w, v1.x, v1.y, v1.z, v1.w};
            unsigned long long sv[8];
#pragma unroll
            for (int p = 0; p < 8; p++) sv[p] = splat2(vr[p]);
#pragma unroll
            for (int q = 0; q < 4; q++)
#pragma unroll
                for (int p = 0; p < 8; p++)
                    ffma2(acc2[q][p], wq[q], sv[p]);
        }
        __syncthreads();
    }

#pragma unroll
    for (int q = 0; q < 4; q++) {
        int co0 = co_base + co8 + 2 * q;
        float b0 = (co0 < Cout) ? bias[co0] : 0.f;
        float b1 = (co0 + 1 < Cout) ? bias[co0 + 1] : 0.f;
#pragma unroll
        for (int p = 0; p < 8; p++) {
            int pix = p0 + p8 + p;
            if (pix < HWN) {
                float2 v = unpack2(acc2[q][p]);
                if (co0 < Cout)
                    out[((size_t)b * Cout + co0) * HWN + pix] = v.x + b0;
                if (co0 + 1 < Cout)
                    out[((size_t)b * Cout + co0 + 1) * HWN + pix] = v.y + b1;
            }
        }
    }
}

// ---------------------------------------------------------------------------
// delta head
// ---------------------------------------------------------------------------
__global__ void delta_kernel(const float* __restrict__ boxreg,
                             const float* __restrict__ refine,
                             float* __restrict__ out)
{
    int t = blockIdx.x * blockDim.x + threadIdx.x;
    if (t >= BATCH * NA * HWN) return;
    int pix = t % HWN;
    int r = t / HWN;
    int a = r % NA;
    int b = r / NA;
    size_t base = ((size_t)b * 36 + a * 4) * HWN + pix;
    float o10 = boxreg[base], o11 = boxreg[base + HWN];
    float o12 = boxreg[base + 2 * HWN], o13 = boxreg[base + 3 * HWN];
    float o20 = refine[base], o21 = refine[base + HWN];
    float o22 = refine[base + 2 * HWN], o23 = refine[base + 3 * HWN];
    out[base]           = o10 + expf(o12) * o20;
    out[base + HWN]     = o11 + expf(o13) * o21;
    out[base + 2 * HWN] = o12 + o22;
    out[base + 3 * HWN] = o13 + o23;
}

// ---------------------------------------------------------------------------
// launch
// ---------------------------------------------------------------------------
extern "C" void kernel_launch(void* const* d_in, const int* in_sizes, int n_in,
                              void* d_out, int out_size)
{
    const float* x       = (const float*)d_in[0];
    const float* cls_w   = (const float*)d_in[1];
    const float* cls_b   = (const float*)d_in[2];
    const float* reg_w   = (const float*)d_in[3];
    const float* reg_b   = (const float*)d_in[4];
    const float* pred_w  = (const float*)d_in[5];
    const float* pred_b  = (const float*)d_in[6];
    const float* dcls_w  = (const float*)d_in[7];
    const float* dreg_w  = (const float*)d_in[8];
    const float* logit_w = (const float*)d_in[9];
    const float* logit_b = (const float*)d_in[10];
    const float* refine_w = (const float*)d_in[11];
    const float* refine_b = (const float*)d_in[12];
    float* out = (float*)d_out;

    float *t0, *t1, *t2, *t3, *boxreg, *dcls, *dreg, *refine;
    cudaGetSymbolAddress((void**)&t0, g_t0);
    cudaGetSymbolAddress((void**)&t1, g_t1);
    cudaGetSymbolAddress((void**)&t2, g_t2);
    cudaGetSymbolAddress((void**)&t3, g_t3);
    cudaGetSymbolAddress((void**)&boxreg, g_boxreg);
    cudaGetSymbolAddress((void**)&dcls, g_dcls);
    cudaGetSymbolAddress((void**)&dreg, g_dreg);
    cudaGetSymbolAddress((void**)&refine, g_refine);

    const size_t WSTEP = (size_t)C * C * 9;
    dim3 cgrid(2, 25, 4 * BATCH);   // x: 2x64 cols, y: 25x4 rows, z: b*nco

    conv3x3_kernel<<<cgrid, 256>>>(x,  cls_w + 0 * WSTEP, cls_b + 0 * C, t0, C, C, 1);
    conv3x3_kernel<<<cgrid, 256>>>(t0, cls_w + 1 * WSTEP, cls_b + 1 * C, t1, C, C, 1);
    conv3x3_kernel<<<cgrid, 256>>>(t1, cls_w + 2 * WSTEP, cls_b + 2 * C, t0, C, C, 1);
    conv3x3_kernel<<<cgrid, 256>>>(t0, cls_w + 3 * WSTEP, cls_b + 3 * C, t1, C, C, 1);
    conv3x3_kernel<<<cgrid, 256>>>(x,  reg_w + 0 * WSTEP, reg_b + 0 * C, t2, C, C, 1);
    conv3x3_kernel<<<cgrid, 256>>>(t2, reg_w + 1 * WSTEP, reg_b + 1 * C, t3, C, C, 1);
    conv3x3_kernel<<<cgrid, 256>>>(t3, reg_w + 2 * WSTEP, reg_b + 2 * C, t2, C, C, 1);
    conv3x3_kernel<<<cgrid, 256>>>(t2, reg_w + 3 * WSTEP, reg_b + 3 * C, t3, C, C, 1);

    dim3 pgrid(2, 25, 1 * BATCH);
    conv3x3_kernel<<<pgrid, 256>>>(t3, pred_w, pred_b, boxreg, C, 36, 0);

    cudaFuncSetAttribute(deform_kernel,
                         cudaFuncAttributeMaxDynamicSharedMemorySize, D_SMEM);
    dim3 dgrid((IW + 15) / 16, (IH + 7) / 8, NA * BATCH * 2);
    deform_kernel<<<dgrid, 256, D_SMEM>>>(t1, boxreg, dcls_w, dcls);
    deform_kernel<<<dgrid, 256, D_SMEM>>>(t3, boxreg, dreg_w, dreg);

    dim3 lgrid((HWN + 255) / 256, (720 + 63) / 64, BATCH);
    conv1x1_kernel<<<lgrid, 256>>>(dcls, logit_w, logit_b, out, 720);
    dim3 rgrid((HWN + 255) / 256, 1, BATCH);
    conv1x1_kernel<<<rgrid, 256>>>(dreg, refine_w, refine_b, refine, 36);

    delta_kernel<<<(BATCH * NA * HWN + 255) / 256, 256>>>(
        boxreg, refine, out + (size_t)BATCH * 720 * HWN);
}

// round 7
// speedup vs baseline: 1.7435x; 1.2538x over previous
#include <cuda_runtime.h>
#include <math.h>

// ---------------------------------------------------------------------------
// Problem constants
// ---------------------------------------------------------------------------
constexpr int IH = 100, IW = 100, HWN = IH * IW;
constexpr int BATCH = 2;
constexpr int NA = 9;
constexpr int C = 256;
constexpr int KTOT = NA * C;   // 2304

// ---------------------------------------------------------------------------
// Scratch
// ---------------------------------------------------------------------------
__device__ float g_t0[BATCH * C * HWN];
__device__ float g_t1[BATCH * C * HWN];
__device__ float g_t2[BATCH * C * HWN];
__device__ float g_t3[BATCH * C * HWN];
__device__ float g_boxreg[BATCH * 36 * HWN];
__device__ float g_dcls[NA * BATCH * C * HWN];
__device__ float g_dreg[NA * BATCH * C * HWN];
__device__ float g_refine[BATCH * 36 * HWN];
__device__ float g_wtc[C * C * 9];   // dcls_w transposed [ci][k][co]
__device__ float g_wtr[C * C * 9];   // dreg_w transposed

// ---------------------------------------------------------------------------
// Packed fp32x2 helpers
// ---------------------------------------------------------------------------
__device__ __forceinline__ unsigned long long splat2(float x) {
    unsigned long long r;
    asm("mov.b64 %0, {%1, %1};" : "=l"(r) : "f"(x));
    return r;
}
__device__ __forceinline__ void ffma2(unsigned long long& acc,
                                      unsigned long long a,
                                      unsigned long long b) {
    asm("fma.rn.f32x2 %0, %1, %2, %0;" : "+l"(acc) : "l"(a), "l"(b));
}
__device__ __forceinline__ float2 unpack2(unsigned long long v) {
    float2 f;
    asm("mov.b64 {%0, %1}, %2;" : "=f"(f.x), "=f"(f.y) : "l"(v));
    return f;
}

// ---------------------------------------------------------------------------
// Feature transpose: [C][HWN] -> [HWN][C] per batch
// ---------------------------------------------------------------------------
__global__ void __launch_bounds__(256) ftrans_kernel(
    const float* __restrict__ in, float* __restrict__ out)
{
    __shared__ float t[32][33];
    const int b = blockIdx.z;
    const int p0 = blockIdx.x * 32, c0 = blockIdx.y * 32;
    const int tx = threadIdx.x & 31, ty = threadIdx.x >> 5;  // 32 x 8
#pragma unroll
    for (int i = 0; i < 32; i += 8) {
        int c = c0 + ty + i, p = p0 + tx;
        t[ty + i][tx] = (p < HWN) ? in[((size_t)b * C + c) * HWN + p] : 0.f;
    }
    __syncthreads();
#pragma unroll
    for (int i = 0; i < 32; i += 8) {
        int p = p0 + ty + i, c = c0 + tx;
        if (p < HWN)
            out[((size_t)b * HWN + p) * C + c] = t[tx][ty + i];
    }
}

// ---------------------------------------------------------------------------
// Weight transpose: [co][ci][k] -> [ci*9+k][co]
// ---------------------------------------------------------------------------
__global__ void __launch_bounds__(256) wtrans_kernel(
    const float* __restrict__ w, float* __restrict__ wt)
{
    int i = blockIdx.x * 256 + threadIdx.x;
    if (i < C * C * 9) {
        int co = i / (C * 9);
        int r = i % (C * 9);
        wt[(size_t)r * C + co] = w[i];
    }
}

// ---------------------------------------------------------------------------
// 3x3 conv, pad=1.  Block: 64 co x (4 rows x 64 cols).  256 thr, 8co x 8px.
// CIT=16, dynamic smem.
// ---------------------------------------------------------------------------
constexpr int CV_CIT = 16;
constexpr int CV_SIN = CV_CIT * 6 * 72;                 // 6912 floats
constexpr int CV_SMEM = (CV_SIN + CV_CIT * 9 * 64) * 4; // 64512 B

__global__ void __launch_bounds__(256) conv3x3_kernel(
    const float* __restrict__ in, const float* __restrict__ wgt,
    const float* __restrict__ bias, float* __restrict__ out,
    int Cin, int Cout, int relu)
{
    extern __shared__ unsigned char smraw[];
    float (*s_in)[6][72] = (float(*)[6][72])smraw;
    float (*s_w)[9][64] = (float(*)[9][64])(smraw + CV_SIN * 4);

    const int nco = (Cout + 63) / 64;
    const int z = blockIdx.z;
    const int b = z / nco;
    const int co_base = (z % nco) * 64;
    const int tx0 = blockIdx.x * 64;
    const int ty0 = blockIdx.y * 4;

    const int tid = threadIdx.x;
    const int warp = tid >> 5;
    const int lane = tid & 31;
    const int cog8 = warp * 8;
    const int pr = lane >> 3;
    const int pc8 = (lane & 7) * 8;

    unsigned long long acc2[4][8];
#pragma unroll
    for (int q = 0; q < 4; q++)
#pragma unroll
        for (int p = 0; p < 8; p++) acc2[q][p] = 0ull;

    for (int ci0 = 0; ci0 < Cin; ci0 += CV_CIT) {
        for (int e = tid; e < CV_CIT * 6 * 66; e += 256) {
            int ci = e / (6 * 66);
            int r = e % (6 * 66);
            int iy = r / 66, ix = r % 66;
            int gy = ty0 + iy - 1, gx = tx0 + ix - 1;
            float v = 0.f;
            if (gy >= 0 && gy < IH && gx >= 0 && gx < IW)
                v = in[(((size_t)b * Cin + ci0 + ci) * IH + gy) * IW + gx];
            s_in[ci][iy][ix] = v;
        }
        for (int e = tid; e < CV_CIT * 9 * 64; e += 256) {
            int ci = e / 576;
            int k = (e >> 6) % 9;
            int co = e & 63;
            float v = 0.f;
            int gco = co_base + co;
            if (gco < Cout)
                v = wgt[(((size_t)gco * Cin) + ci0 + ci) * 9 + k];
            s_w[ci][k][co] = v;
        }
        __syncthreads();

#pragma unroll 2
        for (int ci = 0; ci < CV_CIT; ci++) {
#pragma unroll
            for (int ky = 0; ky < 3; ky++) {
                const float* rp = &s_in[ci][pr + ky][pc8];
                float4 a0 = *(const float4*)(rp);
                float4 a1 = *(const float4*)(rp + 4);
                float4 a2 = *(const float4*)(rp + 8);
                float r12[12] = {a0.x, a0.y, a0.z, a0.w,
                                 a1.x, a1.y, a1.z, a1.w,
                                 a2.x, a2.y, a2.z, a2.w};
                unsigned long long s12[12];
#pragma unroll
                for (int j = 0; j < 12; j++) s12[j] = splat2(r12[j]);
#pragma unroll
                for (int kx = 0; kx < 3; kx++) {
                    const ulonglong2* wp =
                        (const ulonglong2*)&s_w[ci][ky * 3 + kx][cog8];
                    ulonglong2 wA = wp[0];
                    ulonglong2 wB = wp[1];
                    unsigned long long wq[4] = {wA.x, wA.y, wB.x, wB.y};
#pragma unroll
                    for (int q = 0; q < 4; q++)
#pragma unroll
                        for (int p = 0; p < 8; p++)
                            ffma2(acc2[q][p], wq[q], s12[p + kx]);
                }
            }
        }
        __syncthreads();
    }

    const int gy = ty0 + pr;
#pragma unroll
    for (int q = 0; q < 4; q++) {
        int co0 = co_base + cog8 + 2 * q;
        float b0 = (bias && co0 < Cout) ? bias[co0] : 0.f;
        float b1 = (bias && co0 + 1 < Cout) ? bias[co0 + 1] : 0.f;
#pragma unroll
        for (int p = 0; p < 8; p++) {
            int gx = tx0 + pc8 + p;
            if (gy < IH && gx < IW) {
                float2 v = unpack2(acc2[q][p]);
                if (co0 < Cout) {
                    float r = v.x + b0;
                    if (relu) r = fmaxf(r, 0.f);
                    out[(((size_t)b * Cout + co0) * IH + gy) * IW + gx] = r;
                }
                if (co0 + 1 < Cout) {
                    float r = v.y + b1;
                    if (relu) r = fmaxf(r, 0.f);
                    out[(((size_t)b * Cout + co0 + 1) * IH + gy) * IW + gx] = r;
                }
            }
        }
    }
}

// ---------------------------------------------------------------------------
// Deformable conv v1: block = 256 co x 128 px (8 rows x 16 cols), 512 thr.
// featT: [HW][C] transposed features -> float4 gathers (4 channels/LDG.128)
// wT: [ci*9+k][co] transposed weights -> contiguous smem staging
// ---------------------------------------------------------------------------
constexpr int DN_PX = 128;
constexpr int DN_NS = 9 * DN_PX;                 // 1152
constexpr int DN_CIT = 4;
constexpr int DN_OFF_B = 4 * DN_NS * 2;          // 9216
constexpr int DN_WT_B = 4 * DN_NS * 4;           // 18432
constexpr int DN_V_B = DN_CIT * DN_NS * 4;       // 18432
constexpr int DN_W_B = DN_CIT * 9 * 256 * 4;     // 36864
constexpr int DN_SMEM = DN_OFF_B + DN_WT_B + DN_V_B + DN_W_B;  // 82944

__global__ void __launch_bounds__(512) deform_kernel(
    const float* __restrict__ featT, const float* __restrict__ boxreg,
    const float* __restrict__ wT, float* __restrict__ out)
{
    extern __shared__ unsigned char smraw[];
    short* s_off = (short*)smraw;                               // [4][1152]
    float* s_wt  = (float*)(smraw + DN_OFF_B);                  // [4][1152]
    float* s_v   = (float*)(smraw + DN_OFF_B + DN_WT_B);        // [CIT][1152]
    float* s_w   = (float*)(smraw + DN_OFF_B + DN_WT_B + DN_V_B); // [CIT*9][256]

    const int z = blockIdx.z;          // 0..17 == n == a*BATCH + b
    const int jb = z & 1;              // feature batch
    const int x0 = blockIdx.x * 16, y0 = blockIdx.y * 8;
    const int tid = threadIdx.x;

    const int bn = z / 9, an = z % 9;  // box_reg batch/anchor (reshape twist)

    // ---- phase 0: bilinear sample precompute (128 px x 9 k x 4 corners)
    {
        int px = tid & 127, quarter = tid >> 7;   // 4 quarters split k-space
        int row = px >> 4, col = px & 15;
        int y = y0 + row, x = x0 + col;
        bool pv = (y < IH) && (x < IW);
        float c0 = 0.f, c1 = 0.f, c2 = 0.f, c3 = 0.f;
        if (pv) {
            const float* rp = boxreg + ((size_t)bn * 36 + an * 4) * HWN + y * IW + x;
            c0 = rp[0]; c1 = rp[HWN]; c2 = rp[2 * HWN]; c3 = rp[3 * HWN];
        }
        float size = 2.f * exp2f((float)(an / 3) * (1.f / 3.f));
        int ari = an % 3;
        float ar = (ari == 0) ? 0.5f : (ari == 1 ? 1.f : 2.f);
        float wa = sqrtf(size * size / ar);
        float ha = ar * wa;
        float e2 = expf(c2), e3 = expf(c3);
        float tlx = wa * c0 - 0.5f * wa * e2, whx = wa * e2;
        float tly = ha * c1 - 0.5f * ha * e3, why = ha * e3;
        for (int k = quarter; k < 9; k += 4) {
            int ki = k / 3, kj = k % 3;
            float gx = tlx + whx * (0.5f * kj);
            float gy = tly + why * (0.5f * ki);
            float py = (float)y + gx;   // flip(2): x-grid drives y samples
            float pxx = (float)x + gy;
            float fy = floorf(py), fx = floorf(pxx);
            float ly = py - fy, lx = pxx - fx;
            int iy0 = (int)fy, ix0 = (int)fx;
#pragma unroll
            for (int c = 0; c < 4; c++) {
                int dy = c >> 1, dx = c & 1;
                int yy = iy0 + dy, xx = ix0 + dx;
                bool vc = pv && (yy >= 0) && (yy < IH) && (xx >= 0) && (xx < IW);
                float wv = (dy ? ly : 1.f - ly) * (dx ? lx : 1.f - lx);
                wv = vc ? wv : 0.f;
                int yc = min(max(yy, 0), IH - 1);
                int xc = min(max(xx, 0), IW - 1);
                s_off[c * DN_NS + k * 128 + px] = (short)(yc * IW + xc);
                s_wt[c * DN_NS + k * 128 + px] = wv;
            }
        }
    }
    __syncthreads();

    unsigned long long acc2[4][8];
#pragma unroll
    for (int q = 0; q < 4; q++)
#pragma unroll
        for (int p = 0; p < 8; p++) acc2[q][p] = 0ull;

    const int cog8 = (tid >> 4) * 8;   // 32 co-groups of 8
    const int p8x = (tid & 15) * 8;    // 16 px-groups of 8
    const float* fb = featT + (size_t)jb * HWN * C;

    for (int ci0 = 0; ci0 < C; ci0 += DN_CIT) {
        // stage weights: contiguous block of 4*9*256 floats
        {
            const float4* wsrc =
                reinterpret_cast<const float4*>(wT + (size_t)ci0 * 9 * 256);
            float4* wdst = (float4*)s_w;
            for (int e = tid; e < DN_CIT * 9 * 64; e += 512)
                wdst[e] = wsrc[e];
        }
        // gather: one float4 (4 channels) per sample per corner
        for (int s = tid; s < DN_NS; s += 512) {
            float4 a = make_float4(0.f, 0.f, 0.f, 0.f);
#pragma unroll
            for (int c = 0; c < 4; c++) {
                int off = s_off[c * DN_NS + s];
                float wv = s_wt[c * DN_NS + s];
                float4 g = *reinterpret_cast<const float4*>(
                    fb + (size_t)off * C + ci0);
                a.x = fmaf(wv, g.x, a.x);
                a.y = fmaf(wv, g.y, a.y);
                a.z = fmaf(wv, g.z, a.z);
                a.w = fmaf(wv, g.w, a.w);
            }
            s_v[s] = a.x;
            s_v[DN_NS + s] = a.y;
            s_v[2 * DN_NS + s] = a.z;
            s_v[3 * DN_NS + s] = a.w;
        }
        __syncthreads();

        for (int ci = 0; ci < DN_CIT; ci++) {
#pragma unroll
            for (int k = 0; k < 9; k++) {
                const ulonglong2* wp =
                    (const ulonglong2*)&s_w[(ci * 9 + k) * 256 + cog8];
                ulonglong2 wA = wp[0];
                ulonglong2 wB = wp[1];
                unsigned long long wq[4] = {wA.x, wA.y, wB.x, wB.y};
                const float4* vp = (const float4*)&s_v[ci * DN_NS + k * 128 + p8x];
                float4 v0 = vp[0], v1 = vp[1];
                float vr[8] = {v0.x, v0.y, v0.z, v0.w, v1.x, v1.y, v1.z, v1.w};
                unsigned long long sv[8];
#pragma unroll
                for (int p = 0; p < 8; p++) sv[p] = splat2(vr[p]);
#pragma unroll
                for (int q = 0; q < 4; q++)
#pragma unroll
                    for (int p = 0; p < 8; p++)
                        ffma2(acc2[q][p], wq[q], sv[p]);
            }
        }
        __syncthreads();
    }

    float* ob = out + (size_t)z * C * HWN;
#pragma unroll
    for (int q = 0; q < 4; q++) {
        int co0 = cog8 + 2 * q;
#pragma unroll
        for (int p = 0; p < 8; p++) {
            int px = p8x + p;
            int y = y0 + (px >> 4), x = x0 + (px & 15);
            if (y < IH && x < IW) {
                float2 v = unpack2(acc2[q][p]);
                ob[(size_t)co0 * HWN + y * IW + x] = v.x;
                ob[(size_t)(co0 + 1) * HWN + y * IW + x] = v.y;
            }
        }
    }
}

// ---------------------------------------------------------------------------
// 1x1 conv with fused input ReLU.  Block: 64 co x 256 px, Kchunk=16.
// ---------------------------------------------------------------------------
__global__ void __launch_bounds__(256) conv1x1_kernel(
    const float* __restrict__ in, const float* __restrict__ wgt,
    const float* __restrict__ bias, float* __restrict__ out, int Cout)
{
    __shared__ __align__(16) float s_in[16][256];
    __shared__ __align__(16) float s_w[16][64];

    const int b = blockIdx.z;
    const int co_base = blockIdx.y * 64;
    const int p0 = blockIdx.x * 256;
    const int tid = threadIdx.x;
    const int warp = tid >> 5;
    const int lane = tid & 31;
    const int co8 = warp * 8;
    const int p8 = lane * 8;

    unsigned long long acc2[4][8];
#pragma unroll
    for (int q = 0; q < 4; q++)
#pragma unroll
        for (int p = 0; p < 8; p++) acc2[q][p] = 0ull;

    for (int k0 = 0; k0 < KTOT; k0 += 16) {
        for (int e = tid; e < 16 * 256; e += 256) {
            int kk = e >> 8, p = e & 255;
            int k = k0 + kk;
            int aidx = k >> 8, c = k & 255;
            int pix = p0 + p;
            float v = 0.f;
            if (pix < HWN)
                v = in[((size_t)(aidx * 2 + b) * C + c) * HWN + pix];
            s_in[kk][p] = fmaxf(v, 0.f);
        }
        for (int e = tid; e < 16 * 64; e += 256) {
            int kk = e >> 6, co = e & 63;
            float wv = 0.f;
            if (co_base + co < Cout)
                wv = wgt[(size_t)(co_base + co) * KTOT + k0 + kk];
            s_w[kk][co] = wv;
        }
        __syncthreads();

#pragma unroll 4
        for (int kk = 0; kk < 16; kk++) {
            const ulonglong2* wp = (const ulonglong2*)&s_w[kk][co8];
            ulonglong2 wA = wp[0];
            ulonglong2 wB = wp[1];
            unsigned long long wq[4] = {wA.x, wA.y, wB.x, wB.y};
            const float4* vp = (const float4*)&s_in[kk][p8];
            float4 v0 = vp[0], v1 = vp[1];
            float vr[8] = {v0.x, v0.y, v0.z, v0.w, v1.x, v1.y, v1.z, v1.w};
            unsigned long long sv[8];
#pragma unroll
            for (int p = 0; p < 8; p++) sv[p] = splat2(vr[p]);
#pragma unroll
            for (int q = 0; q < 4; q++)
#pragma unroll
                for (int p = 0; p < 8; p++)
                    ffma2(acc2[q][p], wq[q], sv[p]);
        }
        __syncthreads();
    }

#pragma unroll
    for (int q = 0; q < 4; q++) {
        int co0 = co_base + co8 + 2 * q;
        float b0 = (co0 < Cout) ? bias[co0] : 0.f;
        float b1 = (co0 + 1 < Cout) ? bias[co0 + 1] : 0.f;
#pragma unroll
        for (int p = 0; p < 8; p++) {
            int pix = p0 + p8 + p;
            if (pix < HWN) {
                float2 v = unpack2(acc2[q][p]);
                if (co0 < Cout)
                    out[((size_t)b * Cout + co0) * HWN + pix] = v.x + b0;
                if (co0 + 1 < Cout)
                    out[((size_t)b * Cout + co0 + 1) * HWN + pix] = v.y + b1;
            }
        }
    }
}

// ---------------------------------------------------------------------------
// delta head
// ---------------------------------------------------------------------------
__global__ void delta_kernel(const float* __restrict__ boxreg,
                             const float* __restrict__ refine,
                             float* __restrict__ out)
{
    int t = blockIdx.x * blockDim.x + threadIdx.x;
    if (t >= BATCH * NA * HWN) return;
    int pix = t % HWN;
    int r = t / HWN;
    int a = r % NA;
    int b = r / NA;
    size_t base = ((size_t)b * 36 + a * 4) * HWN + pix;
    float o10 = boxreg[base], o11 = boxreg[base + HWN];
    float o12 = boxreg[base + 2 * HWN], o13 = boxreg[base + 3 * HWN];
    float o20 = refine[base], o21 = refine[base + HWN];
    float o22 = refine[base + 2 * HWN], o23 = refine[base + 3 * HWN];
    out[base]           = o10 + expf(o12) * o20;
    out[base + HWN]     = o11 + expf(o13) * o21;
    out[base + 2 * HWN] = o12 + o22;
    out[base + 3 * HWN] = o13 + o23;
}

// ---------------------------------------------------------------------------
// launch
// ---------------------------------------------------------------------------
extern "C" void kernel_launch(void* const* d_in, const int* in_sizes, int n_in,
                              void* d_out, int out_size)
{
    const float* x       = (const float*)d_in[0];
    const float* cls_w   = (const float*)d_in[1];
    const float* cls_b   = (const float*)d_in[2];
    const float* reg_w   = (const float*)d_in[3];
    const float* reg_b   = (const float*)d_in[4];
    const float* pred_w  = (const float*)d_in[5];
    const float* pred_b  = (const float*)d_in[6];
    const float* dcls_w  = (const float*)d_in[7];
    const float* dreg_w  = (const float*)d_in[8];
    const float* logit_w = (const float*)d_in[9];
    const float* logit_b = (const float*)d_in[10];
    const float* refine_w = (const float*)d_in[11];
    const float* refine_b = (const float*)d_in[12];
    float* out = (float*)d_out;

    float *t0, *t1, *t2, *t3, *boxreg, *dcls, *dreg, *refine, *wtc, *wtr;
    cudaGetSymbolAddress((void**)&t0, g_t0);
    cudaGetSymbolAddress((void**)&t1, g_t1);
    cudaGetSymbolAddress((void**)&t2, g_t2);
    cudaGetSymbolAddress((void**)&t3, g_t3);
    cudaGetSymbolAddress((void**)&boxreg, g_boxreg);
    cudaGetSymbolAddress((void**)&dcls, g_dcls);
    cudaGetSymbolAddress((void**)&dreg, g_dreg);
    cudaGetSymbolAddress((void**)&refine, g_refine);
    cudaGetSymbolAddress((void**)&wtc, g_wtc);
    cudaGetSymbolAddress((void**)&wtr, g_wtr);

    cudaFuncSetAttribute(conv3x3_kernel,
                         cudaFuncAttributeMaxDynamicSharedMemorySize, CV_SMEM);
    cudaFuncSetAttribute(deform_kernel,
                         cudaFuncAttributeMaxDynamicSharedMemorySize, DN_SMEM);

    const size_t WSTEP = (size_t)C * C * 9;
    dim3 cgrid(2, 25, 4 * BATCH);   // x: 2x64 cols, y: 25x4 rows, z: b*nco

    // weight transposes (independent; run first)
    wtrans_kernel<<<(C * C * 9 + 255) / 256, 256>>>(dcls_w, wtc);
    wtrans_kernel<<<(C * C * 9 + 255) / 256, 256>>>(dreg_w, wtr);

    conv3x3_kernel<<<cgrid, 256, CV_SMEM>>>(x,  cls_w + 0 * WSTEP, cls_b + 0 * C, t0, C, C, 1);
    conv3x3_kernel<<<cgrid, 256, CV_SMEM>>>(t0, cls_w + 1 * WSTEP, cls_b + 1 * C, t1, C, C, 1);
    conv3x3_kernel<<<cgrid, 256, CV_SMEM>>>(t1, cls_w + 2 * WSTEP, cls_b + 2 * C, t0, C, C, 1);
    conv3x3_kernel<<<cgrid, 256, CV_SMEM>>>(t0, cls_w + 3 * WSTEP, cls_b + 3 * C, t1, C, C, 1);
    conv3x3_kernel<<<cgrid, 256, CV_SMEM>>>(x,  reg_w + 0 * WSTEP, reg_b + 0 * C, t2, C, C, 1);
    conv3x3_kernel<<<cgrid, 256, CV_SMEM>>>(t2, reg_w + 1 * WSTEP, reg_b + 1 * C, t3, C, C, 1);
    conv3x3_kernel<<<cgrid, 256, CV_SMEM>>>(t3, reg_w + 2 * WSTEP, reg_b + 2 * C, t2, C, C, 1);
    conv3x3_kernel<<<cgrid, 256, CV_SMEM>>>(t2, reg_w + 3 * WSTEP, reg_b + 3 * C, t3, C, C, 1);

    dim3 pgrid(2, 25, 1 * BATCH);
    conv3x3_kernel<<<pgrid, 256, CV_SMEM>>>(t3, pred_w, pred_b, boxreg, C, 36, 0);

    // feature transposes into freed tower buffers: t1 -> t0, t3 -> t2
    dim3 tgrid((HWN + 31) / 32, C / 32, BATCH);
    ftrans_kernel<<<tgrid, 256>>>(t1, t0);
    ftrans_kernel<<<tgrid, 256>>>(t3, t2);

    // deformable convs (featT layout, transposed weights)
    dim3 dgrid((IW + 15) / 16, (IH + 7) / 8, NA * BATCH);
    deform_kernel<<<dgrid, 512, DN_SMEM>>>(t0, boxreg, wtc, dcls);
    deform_kernel<<<dgrid, 512, DN_SMEM>>>(t2, boxreg, wtr, dreg);

    dim3 lgrid((HWN + 255) / 256, (720 + 63) / 64, BATCH);
    conv1x1_kernel<<<lgrid, 256>>>(dcls, logit_w, logit_b, out, 720);
    dim3 rgrid((HWN + 255) / 256, 1, BATCH);
    conv1x1_kernel<<<rgrid, 256>>>(dreg, refine_w, refine_b, refine, 36);

    delta_kernel<<<(BATCH * NA * HWN + 255) / 256, 256>>>(
        boxreg, refine, out + (size_t)BATCH * 720 * HWN);
}

// round 10
// speedup vs baseline: 1.8155x; 1.0413x over previous
#include <cuda_runtime.h>
#include <math.h>

// ---------------------------------------------------------------------------
// Problem constants
// ---------------------------------------------------------------------------
constexpr int IH = 100, IW = 100, HWN = IH * IW;
constexpr int BATCH = 2;
constexpr int NA = 9;
constexpr int C = 256;
constexpr int KTOT = NA * C;   // 2304

// ---------------------------------------------------------------------------
// Scratch
// ---------------------------------------------------------------------------
__device__ float g_t0[BATCH * C * HWN];
__device__ float g_t1[BATCH * C * HWN];
__device__ float g_t2[BATCH * C * HWN];
__device__ float g_t3[BATCH * C * HWN];
__device__ float g_boxreg[BATCH * 36 * HWN];
__device__ float g_dcls[NA * BATCH * C * HWN];
__device__ float g_dreg[NA * BATCH * C * HWN];
__device__ float g_refine[BATCH * 36 * HWN];
__device__ float g_wtc[C * C * 9];   // dcls_w transposed [ci][k][co]
__device__ float g_wtr[C * C * 9];   // dreg_w transposed

// ---------------------------------------------------------------------------
// Packed fp32x2 helpers
// ---------------------------------------------------------------------------
__device__ __forceinline__ unsigned long long splat2(float x) {
    unsigned long long r;
    asm("mov.b64 %0, {%1, %1};" : "=l"(r) : "f"(x));
    return r;
}
__device__ __forceinline__ void ffma2(unsigned long long& acc,
                                      unsigned long long a,
                                      unsigned long long b) {
    asm("fma.rn.f32x2 %0, %1, %2, %0;" : "+l"(acc) : "l"(a), "l"(b));
}
__device__ __forceinline__ float2 unpack2(unsigned long long v) {
    float2 f;
    asm("mov.b64 {%0, %1}, %2;" : "=f"(f.x), "=f"(f.y) : "l"(v));
    return f;
}

// ---------------------------------------------------------------------------
// Feature transpose: [C][HWN] -> [HWN][C] per batch
// ---------------------------------------------------------------------------
__global__ void __launch_bounds__(256) ftrans_kernel(
    const float* __restrict__ in, float* __restrict__ out)
{
    __shared__ float t[32][33];
    const int b = blockIdx.z;
    const int p0 = blockIdx.x * 32, c0 = blockIdx.y * 32;
    const int tx = threadIdx.x & 31, ty = threadIdx.x >> 5;  // 32 x 8
#pragma unroll
    for (int i = 0; i < 32; i += 8) {
        int c = c0 + ty + i, p = p0 + tx;
        t[ty + i][tx] = (p < HWN) ? in[((size_t)b * C + c) * HWN + p] : 0.f;
    }
    __syncthreads();
#pragma unroll
    for (int i = 0; i < 32; i += 8) {
        int p = p0 + ty + i, c = c0 + tx;
        if (p < HWN)
            out[((size_t)b * HWN + p) * C + c] = t[tx][ty + i];
    }
}

// ---------------------------------------------------------------------------
// Weight transpose: [co][ci][k] -> [ci*9+k][co]
// ---------------------------------------------------------------------------
__global__ void __launch_bounds__(256) wtrans_kernel(
    const float* __restrict__ w, float* __restrict__ wt)
{
    int i = blockIdx.x * 256 + threadIdx.x;
    if (i < C * C * 9) {
        int co = i / (C * 9);
        int r = i % (C * 9);
        wt[(size_t)r * C + co] = w[i];
    }
}

// ---------------------------------------------------------------------------
// 3x3 conv, pad=1.  Block: 64 co x (4 rows x 64 cols).  256 thr, 8co x 8px.
// CIT=16, dynamic smem.
// ---------------------------------------------------------------------------
constexpr int CV_CIT = 16;
constexpr int CV_SIN = CV_CIT * 6 * 72;                 // 6912 floats
constexpr int CV_SMEM = (CV_SIN + CV_CIT * 9 * 64) * 4; // 64512 B

__global__ void __launch_bounds__(256) conv3x3_kernel(
    const float* __restrict__ in, const float* __restrict__ wgt,
    const float* __restrict__ bias, float* __restrict__ out,
    int Cin, int Cout, int relu)
{
    extern __shared__ unsigned char smraw[];
    float (*s_in)[6][72] = (float(*)[6][72])smraw;
    float (*s_w)[9][64] = (float(*)[9][64])(smraw + CV_SIN * 4);

    const int nco = (Cout + 63) / 64;
    const int z = blockIdx.z;
    const int b = z / nco;
    const int co_base = (z % nco) * 64;
    const int tx0 = blockIdx.x * 64;
    const int ty0 = blockIdx.y * 4;

    const int tid = threadIdx.x;
    const int warp = tid >> 5;
    const int lane = tid & 31;
    const int cog8 = warp * 8;
    const int pr = lane >> 3;
    const int pc8 = (lane & 7) * 8;

    unsigned long long acc2[4][8];
#pragma unroll
    for (int q = 0; q < 4; q++)
#pragma unroll
        for (int p = 0; p < 8; p++) acc2[q][p] = 0ull;

    for (int ci0 = 0; ci0 < Cin; ci0 += CV_CIT) {
        for (int e = tid; e < CV_CIT * 6 * 66; e += 256) {
            int ci = e / (6 * 66);
            int r = e % (6 * 66);
            int iy = r / 66, ix = r % 66;
            int gy = ty0 + iy - 1, gx = tx0 + ix - 1;
            float v = 0.f;
            if (gy >= 0 && gy < IH && gx >= 0 && gx < IW)
                v = in[(((size_t)b * Cin + ci0 + ci) * IH + gy) * IW + gx];
            s_in[ci][iy][ix] = v;
        }
        for (int e = tid; e < CV_CIT * 9 * 64; e += 256) {
            int ci = e / 576;
            int k = (e >> 6) % 9;
            int co = e & 63;
            float v = 0.f;
            int gco = co_base + co;
            if (gco < Cout)
                v = wgt[(((size_t)gco * Cin) + ci0 + ci) * 9 + k];
            s_w[ci][k][co] = v;
        }
        __syncthreads();

#pragma unroll 2
        for (int ci = 0; ci < CV_CIT; ci++) {
#pragma unroll
            for (int ky = 0; ky < 3; ky++) {
                const float* rp = &s_in[ci][pr + ky][pc8];
                float4 a0 = *(const float4*)(rp);
                float4 a1 = *(const float4*)(rp + 4);
                float4 a2 = *(const float4*)(rp + 8);
                float r12[12] = {a0.x, a0.y, a0.z, a0.w,
                                 a1.x, a1.y, a1.z, a1.w,
                                 a2.x, a2.y, a2.z, a2.w};
                unsigned long long s12[12];
#pragma unroll
                for (int j = 0; j < 12; j++) s12[j] = splat2(r12[j]);
#pragma unroll
                for (int kx = 0; kx < 3; kx++) {
                    const ulonglong2* wp =
                        (const ulonglong2*)&s_w[ci][ky * 3 + kx][cog8];
                    ulonglong2 wA = wp[0];
                    ulonglong2 wB = wp[1];
                    unsigned long long wq[4] = {wA.x, wA.y, wB.x, wB.y};
#pragma unroll
                    for (int q = 0; q < 4; q++)
#pragma unroll
                        for (int p = 0; p < 8; p++)
                            ffma2(acc2[q][p], wq[q], s12[p + kx]);
                }
            }
        }
        __syncthreads();
    }

    const int gy = ty0 + pr;
#pragma unroll
    for (int q = 0; q < 4; q++) {
        int co0 = co_base + cog8 + 2 * q;
        float b0 = (bias && co0 < Cout) ? bias[co0] : 0.f;
        float b1 = (bias && co0 + 1 < Cout) ? bias[co0 + 1] : 0.f;
#pragma unroll
        for (int p = 0; p < 8; p++) {
            int gx = tx0 + pc8 + p;
            if (gy < IH && gx < IW) {
                float2 v = unpack2(acc2[q][p]);
                if (co0 < Cout) {
                    float r = v.x + b0;
                    if (relu) r = fmaxf(r, 0.f);
                    out[(((size_t)b * Cout + co0) * IH + gy) * IW + gx] = r;
                }
                if (co0 + 1 < Cout) {
                    float r = v.y + b1;
                    if (relu) r = fmaxf(r, 0.f);
                    out[(((size_t)b * Cout + co0 + 1) * IH + gy) * IW + gx] = r;
                }
            }
        }
    }
}

// ---------------------------------------------------------------------------
// Deformable conv v1: block = 256 co x 128 px (8 rows x 16 cols), 512 thr.
// CIT=8, DOUBLE-BUFFERED s_v, weights direct from global (L1 broadcast).
// Gather lane mapping: adjacent lanes read adjacent 32B of one sample row
// -> 16 L1 wavefronts per corner LDG instead of 32.
// ---------------------------------------------------------------------------
constexpr int DN_NS = 9 * 128;                   // 1152 samples
constexpr int DN_CIT = 8;
constexpr int DN_NCH = C / DN_CIT;               // 32 chunks
constexpr int DN_OFF_B = 4 * DN_NS * 2;          // 9216
constexpr int DN_WT_B = 4 * DN_NS * 4;           // 18432
constexpr int DN_VBUF = DN_CIT * DN_NS;          // 9216 floats per buffer
constexpr int DN_SMEM = DN_OFF_B + DN_WT_B + 2 * DN_VBUF * 4;  // 101376

__global__ void __launch_bounds__(512) deform_kernel(
    const float* __restrict__ featT, const float* __restrict__ boxreg,
    const float* __restrict__ wT, float* __restrict__ out)
{
    extern __shared__ unsigned char smraw[];
    short* s_off = (short*)smraw;                        // [4][1152]
    float* s_wt  = (float*)(smraw + DN_OFF_B);           // [4][1152]
    float* s_v   = (float*)(smraw + DN_OFF_B + DN_WT_B); // [2][CIT][1152]

    const int z = blockIdx.z;          // flat n == a*BATCH + b
    const int jb = z & 1;              // feature batch
    const int x0 = blockIdx.x * 16, y0 = blockIdx.y * 8;
    const int tid = threadIdx.x;

    const int bn = z / 9, an = z % 9;  // box_reg batch/anchor (reshape twist)

    // ---- phase 0: bilinear sample precompute (128 px x 9 k x 4 corners)
    {
        int px = tid & 127, quarter = tid >> 7;   // 4 quarters split k-space
        int row = px >> 4, col = px & 15;
        int y = y0 + row, x = x0 + col;
        bool pv = (y < IH) && (x < IW);
        float c0 = 0.f, c1 = 0.f, c2 = 0.f, c3 = 0.f;
        if (pv) {
            const float* rp = boxreg + ((size_t)bn * 36 + an * 4) * HWN + y * IW + x;
            c0 = rp[0]; c1 = rp[HWN]; c2 = rp[2 * HWN]; c3 = rp[3 * HWN];
        }
        float size = 2.f * exp2f((float)(an / 3) * (1.f / 3.f));
        int ari = an % 3;
        float ar = (ari == 0) ? 0.5f : (ari == 1 ? 1.f : 2.f);
        float wa = sqrtf(size * size / ar);
        float ha = ar * wa;
        float e2 = expf(c2), e3 = expf(c3);
        float tlx = wa * c0 - 0.5f * wa * e2, whx = wa * e2;
        float tly = ha * c1 - 0.5f * ha * e3, why = ha * e3;
        for (int k = quarter; k < 9; k += 4) {
            int ki = k / 3, kj = k % 3;
            float gx = tlx + whx * (0.5f * kj);
            float gy = tly + why * (0.5f * ki);
            float py = (float)y + gx;   // flip(2): x-grid drives y samples
            float pxx = (float)x + gy;
            float fy = floorf(py), fx = floorf(pxx);
            float ly = py - fy, lx = pxx - fx;
            int iy0 = (int)fy, ix0 = (int)fx;
#pragma unroll
            for (int c = 0; c < 4; c++) {
                int dy = c >> 1, dx = c & 1;
                int yy = iy0 + dy, xx = ix0 + dx;
                bool vc = pv && (yy >= 0) && (yy < IH) && (xx >= 0) && (xx < IW);
                float wv = (dy ? ly : 1.f - ly) * (dx ? lx : 1.f - lx);
                wv = vc ? wv : 0.f;
                int yc = min(max(yy, 0), IH - 1);
                int xc = min(max(xx, 0), IW - 1);
                s_off[c * DN_NS + k * 128 + px] = (short)(yc * IW + xc);
                s_wt[c * DN_NS + k * 128 + px] = wv;
            }
        }
    }
    __syncthreads();

    unsigned long long acc2[4][8];
#pragma unroll
    for (int q = 0; q < 4; q++)
#pragma unroll
        for (int p = 0; p < 8; p++) acc2[q][p] = 0ull;

    const int cog8 = (tid >> 4) * 8;   // 32 co-groups of 8
    const int p8x = (tid & 15) * 8;    // 16 px-groups of 8
    const float* fb = featT + (size_t)jb * HWN * C;

    // gather one CIT=8 chunk into s_v buffer `buf`.
    // e -> (sample s = e>>1, sub = e&1): lanes pair up on one sample's
    // 32B-contiguous channel range -> 16 wavefronts per corner LDG.
    auto gather = [&](int chunk, int buf) {
        int ci0 = chunk * DN_CIT;
        float* vb = s_v + buf * DN_VBUF;
        for (int e = tid; e < DN_NS * 2; e += 512) {
            int s = e >> 1, sub = e & 1;
            float4 a = make_float4(0.f, 0.f, 0.f, 0.f);
#pragma unroll
            for (int c = 0; c < 4; c++) {
                int off = s_off[c * DN_NS + s];
                float wv = s_wt[c * DN_NS + s];
                float4 g = *reinterpret_cast<const float4*>(
                    fb + (size_t)off * C + ci0 + sub * 4);
                a.x = fmaf(wv, g.x, a.x);
                a.y = fmaf(wv, g.y, a.y);
                a.z = fmaf(wv, g.z, a.z);
                a.w = fmaf(wv, g.w, a.w);
            }
            float* vd = vb + (sub * 4) * DN_NS + s;
            vd[0] = a.x;
            vd[DN_NS] = a.y;
            vd[2 * DN_NS] = a.z;
            vd[3 * DN_NS] = a.w;
        }
    };

    gather(0, 0);
    __syncthreads();

    for (int ch = 0; ch < DN_NCH; ch++) {
        int cur = ch & 1;
        const float* vb = s_v + cur * DN_VBUF;
        const float* wrow = wT + (size_t)(ch * DN_CIT) * 9 * 256;

        for (int ci = 0; ci < DN_CIT; ci++) {
#pragma unroll
            for (int k = 0; k < 9; k++) {
                const float* wp = wrow + (ci * 9 + k) * 256 + cog8;
                ulonglong2 wA = *(const ulonglong2*)(wp);
                ulonglong2 wB = *(const ulonglong2*)(wp + 4);
                unsigned long long wq[4] = {wA.x, wA.y, wB.x, wB.y};
                const float4* vp = (const float4*)&vb[ci * DN_NS + k * 128 + p8x];
                float4 v0 = vp[0], v1 = vp[1];
                float vr[8] = {v0.x, v0.y, v0.z, v0.w, v1.x, v1.y, v1.z, v1.w};
                unsigned long long sv[8];
#pragma unroll
                for (int p = 0; p < 8; p++) sv[p] = splat2(vr[p]);
#pragma unroll
                for (int q = 0; q < 4; q++)
#pragma unroll
                    for (int p = 0; p < 8; p++)
                        ffma2(acc2[q][p], wq[q], sv[p]);
            }
        }
        if (ch + 1 < DN_NCH)
            gather(ch + 1, cur ^ 1);
        __syncthreads();
    }

    float* ob = out + (size_t)z * C * HWN;
#pragma unroll
    for (int q = 0; q < 4; q++) {
        int co0 = cog8 + 2 * q;
#pragma unroll
        for (int p = 0; p < 8; p++) {
            int px = p8x + p;
            int y = y0 + (px >> 4), x = x0 + (px & 15);
            if (y < IH && x < IW) {
                float2 v = unpack2(acc2[q][p]);
                ob[(size_t)co0 * HWN + y * IW + x] = v.x;
                ob[(size_t)(co0 + 1) * HWN + y * IW + x] = v.y;
            }
        }
    }
}

// ---------------------------------------------------------------------------
// 1x1 conv with fused input ReLU.  Block: 64 co x 256 px, Kchunk=16.
// ---------------------------------------------------------------------------
__global__ void __launch_bounds__(256) conv1x1_kernel(
    const float* __restrict__ in, const float* __restrict__ wgt,
    const float* __restrict__ bias, float* __restrict__ out, int Cout)
{
    __shared__ __align__(16) float s_in[16][256];
    __shared__ __align__(16) float s_w[16][64];

    const int b = blockIdx.z;
    const int co_base = blockIdx.y * 64;
    const int p0 = blockIdx.x * 256;
    const int tid = threadIdx.x;
    const int warp = tid >> 5;
    const int lane = tid & 31;
    const int co8 = warp * 8;
    const int p8 = lane * 8;

    unsigned long long acc2[4][8];
#pragma unroll
    for (int q = 0; q < 4; q++)
#pragma unroll
        for (int p = 0; p < 8; p++) acc2[q][p] = 0ull;

    for (int k0 = 0; k0 < KTOT; k0 += 16) {
        for (int e = tid; e < 16 * 256; e += 256) {
            int kk = e >> 8, p = e & 255;
            int k = k0 + kk;
            int aidx = k >> 8, c = k & 255;
            int pix = p0 + p;
            float v = 0.f;
            if (pix < HWN)
                v = in[((size_t)(aidx * 2 + b) * C + c) * HWN + pix];
            s_in[kk][p] = fmaxf(v, 0.f);
        }
        for (int e = tid; e < 16 * 64; e += 256) {
            int kk = e >> 6, co = e & 63;
            float wv = 0.f;
            if (co_base + co < Cout)
                wv = wgt[(size_t)(co_base + co) * KTOT + k0 + kk];
            s_w[kk][co] = wv;
        }
        __syncthreads();

#pragma unroll 4
        for (int kk = 0; kk < 16; kk++) {
            const ulonglong2* wp = (const ulonglong2*)&s_w[kk][co8];
            ulonglong2 wA = wp[0];
            ulonglong2 wB = wp[1];
            unsigned long long wq[4] = {wA.x, wA.y, wB.x, wB.y};
            const float4* vp = (const float4*)&s_in[kk][p8];
            float4 v0 = vp[0], v1 = vp[1];
            float vr[8] = {v0.x, v0.y, v0.z, v0.w, v1.x, v1.y, v1.z, v1.w};
            unsigned long long sv[8];
#pragma unroll
            for (int p = 0; p < 8; p++) sv[p] = splat2(vr[p]);
#pragma unroll
            for (int q = 0; q < 4; q++)
#pragma unroll
                for (int p = 0; p < 8; p++)
                    ffma2(acc2[q][p], wq[q], sv[p]);
        }
        __syncthreads();
    }

#pragma unroll
    for (int q = 0; q < 4; q++) {
        int co0 = co_base + co8 + 2 * q;
        float b0 = (co0 < Cout) ? bias[co0] : 0.f;
        float b1 = (co0 + 1 < Cout) ? bias[co0 + 1] : 0.f;
#pragma unroll
        for (int p = 0; p < 8; p++) {
            int pix = p0 + p8 + p;
            if (pix < HWN) {
                float2 v = unpack2(acc2[q][p]);
                if (co0 < Cout)
                    out[((size_t)b * Cout + co0) * HWN + pix] = v.x + b0;
                if (co0 + 1 < Cout)
                    out[((size_t)b * Cout + co0 + 1) * HWN + pix] = v.y + b1;
            }
        }
    }
}

// ---------------------------------------------------------------------------
// delta head
// ---------------------------------------------------------------------------
__global__ void delta_kernel(const float* __restrict__ boxreg,
                             const float* __restrict__ refine,
                             float* __restrict__ out)
{
    int t = blockIdx.x * blockDim.x + threadIdx.x;
    if (t >= BATCH * NA * HWN) return;
    int pix = t % HWN;
    int r = t / HWN;
    int a = r % NA;
    int b = r / NA;
    size_t base = ((size_t)b * 36 + a * 4) * HWN + pix;
    float o10 = boxreg[base], o11 = boxreg[base + HWN];
    float o12 = boxreg[base + 2 * HWN], o13 = boxreg[base + 3 * HWN];
    float o20 = refine[base], o21 = refine[base + HWN];
    float o22 = refine[base + 2 * HWN], o23 = refine[base + 3 * HWN];
    out[base]           = o10 + expf(o12) * o20;
    out[base + HWN]     = o11 + expf(o13) * o21;
    out[base + 2 * HWN] = o12 + o22;
    out[base + 3 * HWN] = o13 + o23;
}

// ---------------------------------------------------------------------------
// launch
// ---------------------------------------------------------------------------
extern "C" void kernel_launch(void* const* d_in, const int* in_sizes, int n_in,
                              void* d_out, int out_size)
{
    const float* x       = (const float*)d_in[0];
    const float* cls_w   = (const float*)d_in[1];
    const float* cls_b   = (const float*)d_in[2];
    const float* reg_w   = (const float*)d_in[3];
    const float* reg_b   = (const float*)d_in[4];
    const float* pred_w  = (const float*)d_in[5];
    const float* pred_b  = (const float*)d_in[6];
    const float* dcls_w  = (const float*)d_in[7];
    const float* dreg_w  = (const float*)d_in[8];
    const float* logit_w = (const float*)d_in[9];
    const float* logit_b = (const float*)d_in[10];
    const float* refine_w = (const float*)d_in[11];
    const float* refine_b = (const float*)d_in[12];
    float* out = (float*)d_out;

    float *t0, *t1, *t2, *t3, *boxreg, *dcls, *dreg, *refine, *wtc, *wtr;
    cudaGetSymbolAddress((void**)&t0, g_t0);
    cudaGetSymbolAddress((void**)&t1, g_t1);
    cudaGetSymbolAddress((void**)&t2, g_t2);
    cudaGetSymbolAddress((void**)&t3, g_t3);
    cudaGetSymbolAddress((void**)&boxreg, g_boxreg);
    cudaGetSymbolAddress((void**)&dcls, g_dcls);
    cudaGetSymbolAddress((void**)&dreg, g_dreg);
    cudaGetSymbolAddress((void**)&refine, g_refine);
    cudaGetSymbolAddress((void**)&wtc, g_wtc);
    cudaGetSymbolAddress((void**)&wtr, g_wtr);

    cudaFuncSetAttribute(conv3x3_kernel,
                         cudaFuncAttributeMaxDynamicSharedMemorySize, CV_SMEM);
    cudaFuncSetAttribute(deform_kernel,
                         cudaFuncAttributeMaxDynamicSharedMemorySize, DN_SMEM);

    const size_t WSTEP = (size_t)C * C * 9;
    dim3 cgrid(2, 25, 4 * BATCH);   // x: 2x64 cols, y: 25x4 rows, z: b*nco

    // weight transposes (independent; run first)
    wtrans_kernel<<<(C * C * 9 + 255) / 256, 256>>>(dcls_w, wtc);
    wtrans_kernel<<<(C * C * 9 + 255) / 256, 256>>>(dreg_w, wtr);

    conv3x3_kernel<<<cgrid, 256, CV_SMEM>>>(x,  cls_w + 0 * WSTEP, cls_b + 0 * C, t0, C, C, 1);
    conv3x3_kernel<<<cgrid, 256, CV_SMEM>>>(t0, cls_w + 1 * WSTEP, cls_b + 1 * C, t1, C, C, 1);
    conv3x3_kernel<<<cgrid, 256, CV_SMEM>>>(t1, cls_w + 2 * WSTEP, cls_b + 2 * C, t0, C, C, 1);
    conv3x3_kernel<<<cgrid, 256, CV_SMEM>>>(t0, cls_w + 3 * WSTEP, cls_b + 3 * C, t1, C, C, 1);
    conv3x3_kernel<<<cgrid, 256, CV_SMEM>>>(x,  reg_w + 0 * WSTEP, reg_b + 0 * C, t2, C, C, 1);
    conv3x3_kernel<<<cgrid, 256, CV_SMEM>>>(t2, reg_w + 1 * WSTEP, reg_b + 1 * C, t3, C, C, 1);
    conv3x3_kernel<<<cgrid, 256, CV_SMEM>>>(t3, reg_w + 2 * WSTEP, reg_b + 2 * C, t2, C, C, 1);
    conv3x3_kernel<<<cgrid, 256, CV_SMEM>>>(t2, reg_w + 3 * WSTEP, reg_b + 3 * C, t3, C, C, 1);

    dim3 pgrid(2, 25, 1 * BATCH);
    conv3x3_kernel<<<pgrid, 256, CV_SMEM>>>(t3, pred_w, pred_b, boxreg, C, 36, 0);

    // feature transposes into freed tower buffers: t1 -> t0, t3 -> t2
    dim3 tgrid((HWN + 31) / 32, C / 32, BATCH);
    ftrans_kernel<<<tgrid, 256>>>(t1, t0);
    ftrans_kernel<<<tgrid, 256>>>(t3, t2);

    // deformable convs (featT layout, transposed weights)
    dim3 dgrid((IW + 15) / 16, (IH + 7) / 8, NA * BATCH);
    deform_kernel<<<dgrid, 512, DN_SMEM>>>(t0, boxreg, wtc, dcls);
    deform_kernel<<<dgrid, 512, DN_SMEM>>>(t2, boxreg, wtr, dreg);

    dim3 lgrid((HWN + 255) / 256, (720 + 63) / 64, BATCH);
    conv1x1_kernel<<<lgrid, 256>>>(dcls, logit_w, logit_b, out, 720);
    dim3 rgrid((HWN + 255) / 256, 1, BATCH);
    conv1x1_kernel<<<rgrid, 256>>>(dreg, refine_w, refine_b, refine, 36);

    delta_kernel<<<(BATCH * NA * HWN + 255) / 256, 256>>>(
        boxreg, refine, out + (size_t)BATCH * 720 * HWN);
}